// round 16
// baseline (speedup 1.0000x reference)
#include <cuda_runtime.h>

#define FULLMASK 0xffffffffu
#define NTAGS 32
#define BOS_IDX 30
#define EOS_IDX 31
#define L2E 1.4426950408889634f
#define LN2 0.6931471805599453f

typedef unsigned long long ull;

static __device__ __forceinline__ void ffma2(ull& d, ull a, ull b) {
    asm("fma.rn.f32x2 %0, %1, %2, %0;" : "+l"(d) : "l"(a), "l"(b));
}
static __device__ __forceinline__ ull add2(ull a, ull b) {
    ull r; asm("add.rn.f32x2 %0, %1, %2;" : "=l"(r) : "l"(a), "l"(b)); return r;
}
static __device__ __forceinline__ ull mul2(ull a, ull b) {
    ull r; asm("mul.rn.f32x2 %0, %1, %2;" : "=l"(r) : "l"(a), "l"(b)); return r;
}
static __device__ __forceinline__ float ex2_(float x) {
    float r; asm("ex2.approx.f32 %0, %1;" : "=f"(r) : "f"(x)); return r;
}
static __device__ __forceinline__ float lg2_(float x) {
    float r; asm("lg2.approx.f32 %0, %1;" : "=f"(r) : "f"(x)); return r;
}
static __device__ __forceinline__ ull pack2(float x, float y) {
    ull r; asm("mov.b64 %0, {%1,%2};" : "=l"(r) : "f"(x), "f"(y)); return r;
}
static __device__ __forceinline__ void unpack2(ull v, float& x, float& y) {
    asm("mov.b64 {%0,%1}, %2;" : "=f"(x), "=f"(y) : "l"(v));
}
static __device__ __forceinline__ ull shxor2(ull v, int m) {
    float a, b; unpack2(v, a, b);
    return pack2(__shfl_xor_sync(FULLMASK, a, m),
                 __shfl_xor_sync(FULLMASK, b, m));
}

// ---------------------------------------------------------------------------
// FOUR sequences per warp, packed as (bA=(s0,s1), bB=(s2,s3)); fwd/bwd split
// (R9/R13/R15-verified).  Multiplicative lag-1 log2 recurrence, rescale every
// 2nd step (R11..R15-verified).
// Exchange: STS.128 stores tag t's 16B at perm(t) = (t&7)*64 + (t>>3)*16, so
// quarter-split read j (tags 8g+j for group g = lane>>3) is ONE contiguous
// 64B span per LDS.128 (conflict-free, 8-way broadcast = 1 wavefront).
// Quarter dots for rows {l, l^8, l^16, l^24} (R14-verified combine):
//   Q0 = A0 + xor8(A1); Q1 = A2 + xor8(A3); S = Q0 + xor16(Q1)   (per word).
// G coefficients (g,g)-packed once, shared by both words: 64 regs total.
// No __syncwarp (convergent lanes, in-order LSU; R5/R6/R8-verified).
// ---------------------------------------------------------------------------

struct PState4 {
    ull bA, bB;            // packed betas (s0,s1) and (s2,s3)
    float Cs[4];           // accumulated log2 constants
    float sE[4];           // lag anchors
};

template <bool RESCALE, bool BWD>
static __device__ __forceinline__ void crf_step4(
    PState4& st, float e0, float e1, float e2, float e3,
    unsigned stA, unsigned ldA, const ull g[4][8], int anchor)
{
    float K0, K1, K2, K3;
    if (RESCALE) {
        float D0 = lg2_(st.sE[0]);
        float D1 = lg2_(st.sE[1]);
        float D2 = lg2_(st.sE[2]);
        float D3 = lg2_(st.sE[3]);
        st.Cs[0] += D0; st.Cs[1] += D1; st.Cs[2] += D2; st.Cs[3] += D3;
        K0 = ex2_(fmaf(e0, L2E, -D0));
        K1 = ex2_(fmaf(e1, L2E, -D1));
        K2 = ex2_(fmaf(e2, L2E, -D2));
        K3 = ex2_(fmaf(e3, L2E, -D3));
    } else {
        K0 = ex2_(e0 * L2E);
        K1 = ex2_(e1 * L2E);
        K2 = ex2_(e2 * L2E);
        K3 = ex2_(e3 * L2E);
    }
    ull Ka = pack2(K0, K1), Kb = pack2(K2, K3);

    ull xA = BWD ? mul2(st.bA, Ka) : st.bA;     // bwd pre-multiplies
    ull xB = BWD ? mul2(st.bB, Kb) : st.bB;
    asm volatile("st.shared.v2.u64 [%0], {%1,%2};"
                 :: "r"(stA), "l"(xA), "l"(xB) : "memory");

    // 8 LDS.128: load j = tag (8*group + j) -> (pA=(b0,b1), pB=(b2,b3))
    ull A0a = 0ull, A0b = 0ull, A1a = 0ull, A1b = 0ull;
    ull A2a = 0ull, A2b = 0ull, A3a = 0ull, A3b = 0ull;
    #pragma unroll
    for (int j = 0; j < 8; j++) {
        ull pA, pB;
        asm volatile("ld.shared.v2.u64 {%0,%1}, [%2];"
                     : "=l"(pA), "=l"(pB) : "r"(ldA + j * 64));
        ffma2(A0a, g[0][j], pA); ffma2(A0b, g[0][j], pB);
        ffma2(A1a, g[1][j], pA); ffma2(A1b, g[1][j], pB);
        ffma2(A2a, g[2][j], pA); ffma2(A2b, g[2][j], pB);
        ffma2(A3a, g[3][j], pA); ffma2(A3b, g[3][j], pB);
    }

    // combine partials across lane groups (R14-verified; per packed word)
    ull Q0a = add2(A0a, shxor2(A1a, 8));
    ull Q0b = add2(A0b, shxor2(A1b, 8));
    ull Q1a = add2(A2a, shxor2(A3a, 8));
    ull Q1b = add2(A2b, shxor2(A3b, 8));
    ull Sa  = add2(Q0a, shxor2(Q1a, 16));
    ull Sb  = add2(Q0b, shxor2(Q1b, 16));

    if (!RESCALE) {                  // capture anchors (lag-1)
        float s0, s1, s2, s3;
        unpack2(Sa, s0, s1);
        unpack2(Sb, s2, s3);
        st.sE[0] = __shfl_sync(FULLMASK, s0, anchor);
        st.sE[1] = __shfl_sync(FULLMASK, s1, anchor);
        st.sE[2] = __shfl_sync(FULLMASK, s2, anchor);
        st.sE[3] = __shfl_sync(FULLMASK, s3, anchor);
    }
    st.bA = BWD ? Sa : mul2(Sa, Ka);             // fwd post-multiplies
    st.bB = BWD ? Sb : mul2(Sb, Kb);
}

__global__ __launch_bounds__(64, 1) void crf_fb4_kernel(
    const float* __restrict__ emission,   // [B, T, 32]
    const float* __restrict__ trans,      // [32, 32]
    float* __restrict__ out,              // [B]
    int B, int T)
{
    const int lane = threadIdx.x & 31;
    const int dir  = threadIdx.x >> 5;    // 0 = forward, 1 = backward
    const int b0   = blockIdx.x * 4;      // this CTA's 4 sequences

    __shared__ __align__(16) char sexc[2][2][512];  // [warp][buf] exchange
    __shared__ float sfin[2][4][NTAGS];             // [dir][seq][tag]
    __shared__ float scst[2][4];                    // [dir][seq]

    // quarter rows for this lane: rows {l, l^8, l^16, l^24} over cols
    // c0..c0+7 (c0 = 8*(lane>>3)), (v,v)-packed; backward uses G^T.
    const int grp = lane >> 3;
    const int c0 = 8 * grp;
    const int rows[4] = { lane, lane ^ 8, lane ^ 16, lane ^ 24 };
    ull g[4][8];
    #pragma unroll
    for (int r = 0; r < 4; r++) {
        #pragma unroll
        for (int k = 0; k < 8; k++) {
            int c = c0 + k;
            float v = (dir == 0) ? expf(trans[rows[r] * NTAGS + c])
                                 : expf(trans[c * NTAGS + rows[r]]);
            g[r][k] = pack2(v, v);
        }
    }

    const float* em0 = emission + (size_t)(b0 + 0) * T * NTAGS + lane;
    const float* em1 = emission + (size_t)(b0 + 1) * T * NTAGS + lane;
    const float* em2 = emission + (size_t)(b0 + 2) * T * NTAGS + lane;
    const float* em3 = emission + (size_t)(b0 + 3) * T * NTAGS + lane;
    const int M = (T - 1) >> 1;            // fwd: steps 1..M; bwd: T-1..M+1

    // permuted exchange addresses: tag t at (t&7)*64 + (t>>3)*16
    const unsigned sa = (unsigned)__cvta_generic_to_shared(&sexc[dir][0][0]);
    unsigned stA = sa + (unsigned)(((lane & 7) << 6) + (grp << 4));
    unsigned ldA = sa + (unsigned)(grp << 4);

    PState4 st;
    int anchor;
    if (dir == 0) {
        // forward init: step 0 analytic, EOS-anchored, log2 units
        float tb = trans[lane * NTAGS + BOS_IDX];
        float a0 = (em0[0] + tb) * L2E;
        float a1 = (em1[0] + tb) * L2E;
        float a2 = (em2[0] + tb) * L2E;
        float a3 = (em3[0] + tb) * L2E;
        st.Cs[0] = __shfl_sync(FULLMASK, a0, EOS_IDX);
        st.Cs[1] = __shfl_sync(FULLMASK, a1, EOS_IDX);
        st.Cs[2] = __shfl_sync(FULLMASK, a2, EOS_IDX);
        st.Cs[3] = __shfl_sync(FULLMASK, a3, EOS_IDX);
        st.bA = pack2(ex2_(a0 - st.Cs[0]), ex2_(a1 - st.Cs[1]));
        st.bB = pack2(ex2_(a2 - st.Cs[2]), ex2_(a3 - st.Cs[3]));
        st.sE[0] = st.sE[1] = st.sE[2] = st.sE[3] = 1.0f;
        anchor = EOS_IDX;

        float r0[4], r1[4], r2[4], r3[4];
        #pragma unroll
        for (int i = 0; i < 4; i++) {
            int tt = (i + 1 < T) ? (i + 1) : (T - 1);
            r0[i] = em0[(size_t)tt * NTAGS];
            r1[i] = em1[(size_t)tt * NTAGS];
            r2[i] = em2[(size_t)tt * NTAGS];
            r3[i] = em3[(size_t)tt * NTAGS];
        }

        int t = 1;
        #pragma unroll 2
        for (; t + 1 <= M; t += 2) {
            float ea0 = r0[0], ea1 = r1[0], ea2 = r2[0], ea3 = r3[0];
            float eb0 = r0[1], eb1 = r1[1], eb2 = r2[1], eb3 = r3[1];
            r0[0] = r0[2]; r0[1] = r0[3]; r1[0] = r1[2]; r1[1] = r1[3];
            r2[0] = r2[2]; r2[1] = r2[3]; r3[0] = r3[2]; r3[1] = r3[3];
            int q0 = (t + 4 < T) ? (t + 4) : (T - 1);
            int q1 = (t + 5 < T) ? (t + 5) : (T - 1);
            r0[2] = em0[(size_t)q0 * NTAGS]; r0[3] = em0[(size_t)q1 * NTAGS];
            r1[2] = em1[(size_t)q0 * NTAGS]; r1[3] = em1[(size_t)q1 * NTAGS];
            r2[2] = em2[(size_t)q0 * NTAGS]; r2[3] = em2[(size_t)q1 * NTAGS];
            r3[2] = em3[(size_t)q0 * NTAGS]; r3[3] = em3[(size_t)q1 * NTAGS];

            stA ^= 512u; ldA ^= 512u;
            crf_step4<false, false>(st, ea0, ea1, ea2, ea3, stA, ldA, g, anchor);
            stA ^= 512u; ldA ^= 512u;
            crf_step4<true,  false>(st, eb0, eb1, eb2, eb3, stA, ldA, g, anchor);
        }
        if (t <= M) {
            stA ^= 512u; ldA ^= 512u;
            crf_step4<false, false>(st, r0[0], r1[0], r2[0], r3[0],
                                    stA, ldA, g, anchor);
        }
    } else {
        // backward init: v = exp(trans[EOS,:]) (v_EOS = 0), all seqs equal
        float v0 = expf(trans[EOS_IDX * NTAGS + lane]);
        st.bA = pack2(v0, v0);
        st.bB = pack2(v0, v0);
        st.Cs[0] = st.Cs[1] = st.Cs[2] = st.Cs[3] = 0.0f;
        st.sE[0] = st.sE[1] = st.sE[2] = st.sE[3] = 1.0f;
        anchor = 0;
        int nb = T - 1 - M;                // emissions T-1 down to M+1

        float r0[4], r1[4], r2[4], r3[4];
        #pragma unroll
        for (int i = 0; i < 4; i++) {
            int tt = T - 1 - i; if (tt < 0) tt = 0;
            r0[i] = em0[(size_t)tt * NTAGS];
            r1[i] = em1[(size_t)tt * NTAGS];
            r2[i] = em2[(size_t)tt * NTAGS];
            r3[i] = em3[(size_t)tt * NTAGS];
        }

        int i = 0;
        #pragma unroll 2
        for (; i + 1 < nb; i += 2) {
            float ea0 = r0[0], ea1 = r1[0], ea2 = r2[0], ea3 = r3[0];
            float eb0 = r0[1], eb1 = r1[1], eb2 = r2[1], eb3 = r3[1];
            r0[0] = r0[2]; r0[1] = r0[3]; r1[0] = r1[2]; r1[1] = r1[3];
            r2[0] = r2[2]; r2[1] = r2[3]; r3[0] = r3[2]; r3[1] = r3[3];
            int q0 = T - 1 - i - 4; if (q0 < 0) q0 = 0;
            int q1 = T - 1 - i - 5; if (q1 < 0) q1 = 0;
            r0[2] = em0[(size_t)q0 * NTAGS]; r0[3] = em0[(size_t)q1 * NTAGS];
            r1[2] = em1[(size_t)q0 * NTAGS]; r1[3] = em1[(size_t)q1 * NTAGS];
            r2[2] = em2[(size_t)q0 * NTAGS]; r2[3] = em2[(size_t)q1 * NTAGS];
            r3[2] = em3[(size_t)q0 * NTAGS]; r3[3] = em3[(size_t)q1 * NTAGS];

            stA ^= 512u; ldA ^= 512u;
            crf_step4<false, true>(st, ea0, ea1, ea2, ea3, stA, ldA, g, anchor);
            stA ^= 512u; ldA ^= 512u;
            crf_step4<true,  true>(st, eb0, eb1, eb2, eb3, stA, ldA, g, anchor);
        }
        if (i < nb) {
            stA ^= 512u; ldA ^= 512u;
            crf_step4<false, true>(st, r0[0], r1[0], r2[0], r3[0],
                                   stA, ldA, g, anchor);
        }
    }

    // join: Z_s = sum_j beta_fwd,j * v_bwd,j ; log Z = (lg2 + Cf + Cb) ln2
    {
        float f0, f1, f2, f3;
        unpack2(st.bA, f0, f1);
        unpack2(st.bB, f2, f3);
        sfin[dir][0][lane] = f0;
        sfin[dir][1][lane] = f1;
        sfin[dir][2][lane] = f2;
        sfin[dir][3][lane] = f3;
        if (lane < 4) scst[dir][lane] = st.Cs[lane];
    }
    __syncthreads();

    if (dir == 0) {
        #pragma unroll
        for (int s = 0; s < 4; s++) {
            float p = sfin[0][s][lane] * sfin[1][s][lane];
            #pragma unroll
            for (int o = 16; o; o >>= 1)
                p += __shfl_xor_sync(FULLMASK, p, o);
            if (lane == 0 && b0 + s < B)
                out[b0 + s] = (lg2_(p) + scst[0][s] + scst[1][s]) * LN2;
        }
    }
}

extern "C" void kernel_launch(void* const* d_in, const int* in_sizes, int n_in,
                              void* d_out, int out_size)
{
    const float* em = (const float*)d_in[0];
    const float* tr = (const float*)d_in[1];
    long long em_elems = in_sizes[0];
    if (n_in >= 2 && in_sizes[0] == NTAGS * NTAGS && in_sizes[1] > NTAGS * NTAGS) {
        em = (const float*)d_in[1];
        tr = (const float*)d_in[0];
        em_elems = in_sizes[1];
    }

    int B = out_size;
    int T = (int)(em_elems / ((long long)B * NTAGS));

    // 64 threads = 2 warps (fwd + bwd), 4 sequences per CTA
    int blocks = (B + 3) / 4;
    crf_fb4_kernel<<<blocks, 64>>>(em, tr, (float*)d_out, B, T);
}

// round 17
// speedup vs baseline: 1.1521x; 1.1521x over previous
#include <cuda_runtime.h>

#define FULLMASK 0xffffffffu
#define NTAGS 32
#define BOS_IDX 30
#define EOS_IDX 31
#define L2E 1.4426950408889634f
#define LN2 0.6931471805599453f

typedef unsigned long long ull;

static __device__ __forceinline__ void ffma2(ull& d, ull a, ull b) {
    asm("fma.rn.f32x2 %0, %1, %2, %0;" : "+l"(d) : "l"(a), "l"(b));
}
static __device__ __forceinline__ ull add2(ull a, ull b) {
    ull r; asm("add.rn.f32x2 %0, %1, %2;" : "=l"(r) : "l"(a), "l"(b)); return r;
}
static __device__ __forceinline__ ull mul2(ull a, ull b) {
    ull r; asm("mul.rn.f32x2 %0, %1, %2;" : "=l"(r) : "l"(a), "l"(b)); return r;
}
static __device__ __forceinline__ float ex2_(float x) {
    float r; asm("ex2.approx.f32 %0, %1;" : "=f"(r) : "f"(x)); return r;
}
static __device__ __forceinline__ float lg2_(float x) {
    float r; asm("lg2.approx.f32 %0, %1;" : "=f"(r) : "f"(x)); return r;
}
static __device__ __forceinline__ ull pack2(float x, float y) {
    ull r; asm("mov.b64 %0, {%1,%2};" : "=l"(r) : "f"(x), "f"(y)); return r;
}
static __device__ __forceinline__ void unpack2(ull v, float& x, float& y) {
    asm("mov.b64 {%0,%1}, %2;" : "=f"(x), "=f"(y) : "l"(v));
}
static __device__ __forceinline__ ull shxor2(ull v, int m) {
    float a, b; unpack2(v, a, b);
    return pack2(__shfl_xor_sync(FULLMASK, a, m),
                 __shfl_xor_sync(FULLMASK, b, m));
}
static __device__ __forceinline__ float lds32(unsigned a) {
    float v; asm volatile("ld.shared.f32 %0, [%1];" : "=f"(v) : "r"(a));
    return v;
}
#define STS128F(addr, v) \
    asm volatile("st.shared.v4.f32 [%0], {%1,%2,%3,%4};" \
                 :: "r"(addr), "f"((v).x), "f"((v).y), "f"((v).z), "f"((v).w) \
                 : "memory")

// ---------------------------------------------------------------------------
// R14-verified quarter-split packed step (2 seqs per warp as (s0,s1) u64).
// Multiplicative lag-1 log2 recurrence, rescale every 2nd executed step.
// ---------------------------------------------------------------------------
struct PState {
    ull  beta;
    float Cs0, Cs1;
    float sE0, sE1;
};

template <bool RESCALE, bool BWD>
static __device__ __forceinline__ void crf_step(
    PState& st, float e0, float e1, unsigned stA, unsigned ldq,
    const ull g[4][8], int anchor)
{
    float K0, K1;
    if (RESCALE) {
        float D0 = lg2_(st.sE0);
        float D1 = lg2_(st.sE1);
        st.Cs0 += D0; st.Cs1 += D1;
        K0 = ex2_(fmaf(e0, L2E, -D0));
        K1 = ex2_(fmaf(e1, L2E, -D1));
    } else {
        K0 = ex2_(e0 * L2E);
        K1 = ex2_(e1 * L2E);
    }
    ull Kp = pack2(K0, K1);
    ull x = BWD ? mul2(st.beta, Kp) : st.beta;

    asm volatile("st.shared.b64 [%0], %1;" :: "r"(stA), "l"(x) : "memory");

    ull A0 = 0ull, A1 = 0ull, A2 = 0ull, A3 = 0ull;
    #pragma unroll
    for (int j = 0; j < 4; j++) {
        ull pl, ph;
        asm volatile("ld.shared.v2.u64 {%0,%1}, [%2];"
                     : "=l"(pl), "=l"(ph) : "r"(ldq + j * 64));
        ffma2(A0, g[0][2 * j], pl); ffma2(A0, g[0][2 * j + 1], ph);
        ffma2(A1, g[1][2 * j], pl); ffma2(A1, g[1][2 * j + 1], ph);
        ffma2(A2, g[2][2 * j], pl); ffma2(A2, g[2][2 * j + 1], ph);
        ffma2(A3, g[3][2 * j], pl); ffma2(A3, g[3][2 * j + 1], ph);
    }

    ull Q0 = add2(A0, shxor2(A1, 8));
    ull Q1 = add2(A2, shxor2(A3, 8));
    ull S  = add2(Q0, shxor2(Q1, 16));

    if (!RESCALE) {
        float s0, s1; unpack2(S, s0, s1);
        st.sE0 = __shfl_sync(FULLMASK, s0, anchor);
        st.sE1 = __shfl_sync(FULLMASK, s1, anchor);
    }
    st.beta = BWD ? S : mul2(S, Kp);
}

// ---------------------------------------------------------------------------
// Staged kernel (T % 8 == 0, T >= 16): fwd/bwd split, 2 seqs/warp, emissions
// staged through smem in 4-timestep blocks (LDG.128 + STS.128 per block,
// LDS.32 per step) — removes per-step LDG.32 from the MIO budget.
// Exchange/init/join identical to the verified R14 kernel.
// No __syncwarp anywhere in the loops (convergent lanes, in-order LSU).
// ---------------------------------------------------------------------------
__global__ __launch_bounds__(128, 1) void crf_fb2s_kernel(
    const float* __restrict__ emission,   // [B, T, 32]
    const float* __restrict__ trans,      // [32, 32]
    float* __restrict__ out,              // [B]
    int B, int T)
{
    const int lane = threadIdx.x & 31;
    const int wid  = threadIdx.x >> 5;
    const int pair = wid >> 1;
    const int dir  = wid & 1;             // 0 = forward, 1 = backward
    const int b0   = blockIdx.x * 4 + pair * 2;
    const int b1   = b0 + 1;

    __shared__ __align__(16) char  sexc[4][2][256];        // beta exchange
    __shared__ __align__(16) float sem[4][2][2][128];      // [warp][seq][slot]
    __shared__ float sfin[2][2][2][NTAGS];
    __shared__ float scst[2][2][2];

    // quarter rows (R14 verbatim): rows {l, l^8, l^16, l^24} over cols
    // c0..c0+7, (v,v)-packed; backward uses G^T.
    const int c0 = 8 * ((lane >> 3) & 3);
    const int rows[4] = { lane, lane ^ 8, lane ^ 16, lane ^ 24 };
    ull g[4][8];
    #pragma unroll
    for (int r = 0; r < 4; r++) {
        #pragma unroll
        for (int k = 0; k < 8; k++) {
            int c = c0 + k;
            float v = (dir == 0) ? expf(trans[rows[r] * NTAGS + c])
                                 : expf(trans[c * NTAGS + rows[r]]);
            g[r][k] = pack2(v, v);
        }
    }

    const float*  e0p = emission + (size_t)b0 * T * NTAGS;
    const float*  e1p = emission + (size_t)b1 * T * NTAGS;
    const float4* e0q = (const float4*)e0p;
    const float4* e1q = (const float4*)e1p;
    const int M = (T - 1) >> 1;
    const int nblk = T >> 2;

    // exchange addresses (R14 verbatim)
    const unsigned sa = (unsigned)__cvta_generic_to_shared(&sexc[wid][0][0]);
    unsigned stA = sa + (unsigned)((((lane & 7) >> 1) * 64)
                          + ((lane >> 3) * 16) + ((lane & 1) * 8));
    unsigned ldq = sa + (unsigned)(((lane >> 3) & 3) * 16);

    // emission staging addresses: sem[wid][seq][slot][..]
    const unsigned semB = (unsigned)__cvta_generic_to_shared(&sem[wid][0][0][0]);
    const unsigned emSt0 = semB + (unsigned)lane * 16;          // seq0 store
    const unsigned emSt1 = semB + 1024u + (unsigned)lane * 16;  // seq1 store
    const unsigned emLd0 = semB + (unsigned)lane * 4;           // seq0 load
    const unsigned emLd1 = semB + 1024u + (unsigned)lane * 4;   // seq1 load

    PState st;
    int anchor;
    if (dir == 0) {
        // forward init: step 0 analytic, EOS-anchored, log2 units
        float tb = trans[lane * NTAGS + BOS_IDX];
        float a20 = (e0p[lane] + tb) * L2E;
        float a21 = (e1p[lane] + tb) * L2E;
        st.Cs0 = __shfl_sync(FULLMASK, a20, EOS_IDX);
        st.Cs1 = __shfl_sync(FULLMASK, a21, EOS_IDX);
        st.beta = pack2(ex2_(a20 - st.Cs0), ex2_(a21 - st.Cs1));
        st.sE0 = 1.0f; st.sE1 = 1.0f;
        anchor = EOS_IDX;

        // scalar prologue: steps t = 1, 2, 3 (patterns F, T, F)
        float pe0[3], pe1[3];
        #pragma unroll
        for (int t = 1; t <= 3; t++) {
            pe0[t - 1] = e0p[(size_t)t * NTAGS + lane];
            pe1[t - 1] = e1p[(size_t)t * NTAGS + lane];
        }
        // stage block 1 -> slot 1; prefetch block 2
        float4 v0 = e0q[1 * NTAGS + lane];
        float4 v1 = e1q[1 * NTAGS + lane];
        STS128F(emSt0 + 512u, v0);
        STS128F(emSt1 + 512u, v1);
        float4 rv0 = e0q[2 * NTAGS + lane];
        float4 rv1 = e1q[2 * NTAGS + lane];

        stA ^= 256u; ldq ^= 256u;
        crf_step<false, false>(st, pe0[0], pe1[0], stA, ldq, g, anchor);
        stA ^= 256u; ldq ^= 256u;
        crf_step<true,  false>(st, pe0[1], pe1[1], stA, ldq, g, anchor);
        stA ^= 256u; ldq ^= 256u;
        crf_step<false, false>(st, pe0[2], pe1[2], stA, ldq, g, anchor);

        // blocks 1 .. M>>2 (full, 4 steps each, patterns T,F,T,F)
        const int kmax = M >> 2;
        for (int k = 1; k <= kmax; k++) {
            unsigned so = (unsigned)(((k + 1) & 1) * 512);
            STS128F(emSt0 + so, rv0);
            STS128F(emSt1 + so, rv1);
            int nk = (k + 2 < nblk) ? (k + 2) : (nblk - 1);
            rv0 = e0q[(size_t)nk * NTAGS + lane];
            rv1 = e1q[(size_t)nk * NTAGS + lane];

            unsigned lo = (unsigned)((k & 1) * 512);
            stA ^= 256u; ldq ^= 256u;
            crf_step<true,  false>(st, lds32(emLd0 + lo),
                                   lds32(emLd1 + lo), stA, ldq, g, anchor);
            stA ^= 256u; ldq ^= 256u;
            crf_step<false, false>(st, lds32(emLd0 + lo + 128u),
                                   lds32(emLd1 + lo + 128u), stA, ldq, g, anchor);
            stA ^= 256u; ldq ^= 256u;
            crf_step<true,  false>(st, lds32(emLd0 + lo + 256u),
                                   lds32(emLd1 + lo + 256u), stA, ldq, g, anchor);
            stA ^= 256u; ldq ^= 256u;
            crf_step<false, false>(st, lds32(emLd0 + lo + 384u),
                                   lds32(emLd1 + lo + 384u), stA, ldq, g, anchor);
        }
    } else {
        // backward init: v = exp(trans[EOS,:]) (v_EOS = 0)
        float v0i = expf(trans[EOS_IDX * NTAGS + lane]);
        st.beta = pack2(v0i, v0i);
        st.Cs0 = 0.0f; st.Cs1 = 0.0f;
        st.sE0 = 1.0f; st.sE1 = 1.0f;
        anchor = 0;

        // stage block nblk-1; prefetch block nblk-2
        {
            unsigned so = (unsigned)(((nblk - 1) & 1) * 512);
            float4 v0 = e0q[(size_t)(nblk - 1) * NTAGS + lane];
            float4 v1 = e1q[(size_t)(nblk - 1) * NTAGS + lane];
            STS128F(emSt0 + so, v0);
            STS128F(emSt1 + so, v1);
        }
        float4 rv0 = e0q[(size_t)(nblk - 2) * NTAGS + lane];
        float4 rv1 = e1q[(size_t)(nblk - 2) * NTAGS + lane];

        // blocks nblk-1 down to nblk/2 (4 steps each, descending t,
        // patterns F,T,F,T)
        const int kmin = nblk >> 1;
        for (int k = nblk - 1; k >= kmin; k--) {
            unsigned so = (unsigned)(((k - 1) & 1) * 512);
            STS128F(emSt0 + so, rv0);
            STS128F(emSt1 + so, rv1);
            int nk = (k - 2 > 0) ? (k - 2) : 0;
            rv0 = e0q[(size_t)nk * NTAGS + lane];
            rv1 = e1q[(size_t)nk * NTAGS + lane];

            unsigned lo = (unsigned)((k & 1) * 512);
            stA ^= 256u; ldq ^= 256u;
            crf_step<false, true>(st, lds32(emLd0 + lo + 384u),
                                  lds32(emLd1 + lo + 384u), stA, ldq, g, anchor);
            stA ^= 256u; ldq ^= 256u;
            crf_step<true,  true>(st, lds32(emLd0 + lo + 256u),
                                  lds32(emLd1 + lo + 256u), stA, ldq, g, anchor);
            stA ^= 256u; ldq ^= 256u;
            crf_step<false, true>(st, lds32(emLd0 + lo + 128u),
                                  lds32(emLd1 + lo + 128u), stA, ldq, g, anchor);
            stA ^= 256u; ldq ^= 256u;
            crf_step<true,  true>(st, lds32(emLd0 + lo),
                                  lds32(emLd1 + lo), stA, ldq, g, anchor);
        }
    }

    // join (R14 verbatim)
    {
        float f0, f1; unpack2(st.beta, f0, f1);
        sfin[pair][dir][0][lane] = f0;
        sfin[pair][dir][1][lane] = f1;
        if (lane == 0) {
            scst[pair][dir][0] = st.Cs0;
            scst[pair][dir][1] = st.Cs1;
        }
    }
    __syncthreads();

    if (dir == 0) {
        #pragma unroll
        for (int s = 0; s < 2; s++) {
            float p = sfin[pair][0][s][lane] * sfin[pair][1][s][lane];
            #pragma unroll
            for (int o = 16; o; o >>= 1)
                p += __shfl_xor_sync(FULLMASK, p, o);
            if (lane == 0 && b0 + s < B)
                out[b0 + s] = (lg2_(p) + scst[pair][0][s] + scst[pair][1][s])
                              * LN2;
        }
    }
}

// ---------------------------------------------------------------------------
// Fallback (verified R14 kernel, any T): per-step LDG ring.
// ---------------------------------------------------------------------------
__global__ __launch_bounds__(128, 1) void crf_fb2_kernel(
    const float* __restrict__ emission,
    const float* __restrict__ trans,
    float* __restrict__ out,
    int B, int T)
{
    const int lane = threadIdx.x & 31;
    const int wid  = threadIdx.x >> 5;
    const int pair = wid >> 1;
    const int dir  = wid & 1;
    const int b0   = blockIdx.x * 4 + pair * 2;
    const int b1   = b0 + 1;

    __shared__ __align__(16) char sexc[4][2][256];
    __shared__ float sfin[2][2][2][NTAGS];
    __shared__ float scst[2][2][2];

    const int c0 = 8 * ((lane >> 3) & 3);
    const int rows[4] = { lane, lane ^ 8, lane ^ 16, lane ^ 24 };
    ull g[4][8];
    #pragma unroll
    for (int r = 0; r < 4; r++)
        #pragma unroll
        for (int k = 0; k < 8; k++) {
            int c = c0 + k;
            float v = (dir == 0) ? expf(trans[rows[r] * NTAGS + c])
                                 : expf(trans[c * NTAGS + rows[r]]);
            g[r][k] = pack2(v, v);
        }

    const float* em0 = emission + (size_t)b0 * T * NTAGS + lane;
    const float* em1 = emission + (size_t)b1 * T * NTAGS + lane;
    const int M = (T - 1) >> 1;

    const unsigned sa = (unsigned)__cvta_generic_to_shared(&sexc[wid][0][0]);
    unsigned stA = sa + (unsigned)((((lane & 7) >> 1) * 64)
                          + ((lane >> 3) * 16) + ((lane & 1) * 8));
    unsigned ldq = sa + (unsigned)(((lane >> 3) & 3) * 16);

    PState st;
    int anchor;
    if (dir == 0) {
        float tb = trans[lane * NTAGS + BOS_IDX];
        float a20 = (em0[0] + tb) * L2E;
        float a21 = (em1[0] + tb) * L2E;
        st.Cs0 = __shfl_sync(FULLMASK, a20, EOS_IDX);
        st.Cs1 = __shfl_sync(FULLMASK, a21, EOS_IDX);
        st.beta = pack2(ex2_(a20 - st.Cs0), ex2_(a21 - st.Cs1));
        st.sE0 = 1.0f; st.sE1 = 1.0f;
        anchor = EOS_IDX;

        float ra[4], rb[4];
        #pragma unroll
        for (int i = 0; i < 4; i++) {
            int tt = (i + 1 < T) ? (i + 1) : (T - 1);
            ra[i] = em0[(size_t)tt * NTAGS];
            rb[i] = em1[(size_t)tt * NTAGS];
        }
        int t = 1;
        for (; t + 1 <= M; t += 2) {
            float ea0 = ra[0], eb0 = rb[0], ea1 = ra[1], eb1 = rb[1];
            ra[0] = ra[2]; ra[1] = ra[3]; rb[0] = rb[2]; rb[1] = rb[3];
            int q0 = (t + 4 < T) ? (t + 4) : (T - 1);
            int q1 = (t + 5 < T) ? (t + 5) : (T - 1);
            ra[2] = em0[(size_t)q0 * NTAGS]; ra[3] = em0[(size_t)q1 * NTAGS];
            rb[2] = em1[(size_t)q0 * NTAGS]; rb[3] = em1[(size_t)q1 * NTAGS];
            stA ^= 256u; ldq ^= 256u;
            crf_step<false, false>(st, ea0, eb0, stA, ldq, g, anchor);
            stA ^= 256u; ldq ^= 256u;
            crf_step<true,  false>(st, ea1, eb1, stA, ldq, g, anchor);
        }
        if (t <= M) {
            stA ^= 256u; ldq ^= 256u;
            crf_step<false, false>(st, ra[0], rb[0], stA, ldq, g, anchor);
        }
    } else {
        float v0 = expf(trans[EOS_IDX * NTAGS + lane]);
        st.beta = pack2(v0, v0);
        st.Cs0 = 0.0f; st.Cs1 = 0.0f;
        st.sE0 = 1.0f; st.sE1 = 1.0f;
        anchor = 0;
        int nb = T - 1 - M;

        float ra[4], rb[4];
        #pragma unroll
        for (int i = 0; i < 4; i++) {
            int tt = T - 1 - i; if (tt < 0) tt = 0;
            ra[i] = em0[(size_t)tt * NTAGS];
            rb[i] = em1[(size_t)tt * NTAGS];
        }
        int i = 0;
        for (; i + 1 < nb; i += 2) {
            float ea0 = ra[0], eb0 = rb[0], ea1 = ra[1], eb1 = rb[1];
            ra[0] = ra[2]; ra[1] = ra[3]; rb[0] = rb[2]; rb[1] = rb[3];
            int q0 = T - 1 - i - 4; if (q0 < 0) q0 = 0;
            int q1 = T - 1 - i - 5; if (q1 < 0) q1 = 0;
            ra[2] = em0[(size_t)q0 * NTAGS]; ra[3] = em0[(size_t)q1 * NTAGS];
            rb[2] = em1[(size_t)q0 * NTAGS]; rb[3] = em1[(size_t)q1 * NTAGS];
            stA ^= 256u; ldq ^= 256u;
            crf_step<false, true>(st, ea0, eb0, stA, ldq, g, anchor);
            stA ^= 256u; ldq ^= 256u;
            crf_step<true,  true>(st, ea1, eb1, stA, ldq, g, anchor);
        }
        if (i < nb) {
            stA ^= 256u; ldq ^= 256u;
            crf_step<false, true>(st, ra[0], rb[0], stA, ldq, g, anchor);
        }
    }

    {
        float f0, f1; unpack2(st.beta, f0, f1);
        sfin[pair][dir][0][lane] = f0;
        sfin[pair][dir][1][lane] = f1;
        if (lane == 0) {
            scst[pair][dir][0] = st.Cs0;
            scst[pair][dir][1] = st.Cs1;
        }
    }
    __syncthreads();

    if (dir == 0) {
        #pragma unroll
        for (int s = 0; s < 2; s++) {
            float p = sfin[pair][0][s][lane] * sfin[pair][1][s][lane];
            #pragma unroll
            for (int o = 16; o; o >>= 1)
                p += __shfl_xor_sync(FULLMASK, p, o);
            if (lane == 0 && b0 + s < B)
                out[b0 + s] = (lg2_(p) + scst[pair][0][s] + scst[pair][1][s])
                              * LN2;
        }
    }
}

extern "C" void kernel_launch(void* const* d_in, const int* in_sizes, int n_in,
                              void* d_out, int out_size)
{
    const float* em = (const float*)d_in[0];
    const float* tr = (const float*)d_in[1];
    long long em_elems = in_sizes[0];
    if (n_in >= 2 && in_sizes[0] == NTAGS * NTAGS && in_sizes[1] > NTAGS * NTAGS) {
        em = (const float*)d_in[1];
        tr = (const float*)d_in[0];
        em_elems = in_sizes[1];
    }

    int B = out_size;
    int T = (int)(em_elems / ((long long)B * NTAGS));

    int blocks = (B + 3) / 4;
    if (T >= 16 && (T % 8) == 0)
        crf_fb2s_kernel<<<blocks, 128>>>(em, tr, (float*)d_out, B, T);
    else
        crf_fb2_kernel<<<blocks, 128>>>(em, tr, (float*)d_out, B, T);
}